// round 5
// baseline (speedup 1.0000x reference)
#include <cuda_runtime.h>

typedef unsigned long long u64;

#define Bsz 1024
#define Tn  128

__device__ __forceinline__ void fma2(u64 &d, u64 a, u64 b) {
    asm("fma.rn.f32x2 %0, %1, %2, %0;" : "+l"(d) : "l"(a), "l"(b));
}
__device__ __forceinline__ u64 add2(u64 a, u64 b) {
    u64 r; asm("add.rn.f32x2 %0, %1, %2;" : "=l"(r) : "l"(a), "l"(b)); return r;
}
__device__ __forceinline__ u64 pk2(float x) {
    u64 r; unsigned xi = __float_as_uint(x);
    asm("mov.b64 %0, {%1, %2};" : "=l"(r) : "r"(xi), "r"(xi));
    return r;
}
__device__ __forceinline__ float2 upk(u64 v) {
    unsigned lo, hi;
    asm("mov.b64 {%0, %1}, %2;" : "=r"(lo), "=r"(hi) : "l"(v));
    return make_float2(__uint_as_float(lo), __uint_as_float(hi));
}
// fast-math activations (err ~1e-6, tolerance is 1e-3)
__device__ __forceinline__ float eluf(float x)  { return x > 0.f ? x : (__expf(x) - 1.f); }
__device__ __forceinline__ float sigf(float x)  { return __fdividef(1.f, 1.f + __expf(-x)); }
__device__ __forceinline__ float tanf_(float x) {
    x = fminf(fmaxf(x, -20.f), 20.f);
    float t = __expf(2.f * x);
    return __fdividef(t - 1.f, t + 1.f);
}
__device__ __forceinline__ float clipf(float x) { return fminf(fmaxf(x, -7.f), 5.f); }

// ---- weight scratch (zero-init; padded for prefetch overrun) --------------
// Wbig4: [kp][pc(320)][8]: [j*4+c] = Wfused[2kp+j][4pc+c]; kp<128 (pad 132)
__device__ float g_Wbig4[132 * 320 * 8];
// Wpq2: [kp][u(64)][4]: [2j+c] = Wstats[2(u&31)+c][2kp+j] (u<32 P, else Q)
__device__ float g_Wpq2 [128 * 64 * 4];
// Wih2: [kp][p(384)][4]
__device__ float g_Wih2 [20 * 384 * 4];
// emb weights [k][n], padded rows
__device__ float g_We1  [72 * 256];
__device__ float g_We2  [264 * 256];
__device__ float g_Wq1e [264 * 256];
__device__ float g_q1emb[(long)Bsz * Tn * 256];

// ---------------------------------------------------------------------------
__global__ void prep_kernel(const float* __restrict__ Wp1, const float* __restrict__ Wq1,
                            const float* __restrict__ Whh, const float* __restrict__ Wih,
                            const float* __restrict__ Wp2, const float* __restrict__ Wq2,
                            const float* __restrict__ We1, const float* __restrict__ We2)
{
    int tid = blockIdx.x * blockDim.x + threadIdx.x;
    int nt  = gridDim.x * blockDim.x;
    for (int i = tid; i < 128 * 320 * 8; i += nt) {
        int c = i & 3, j = (i >> 2) & 1;
        int pc = (i >> 3) % 320, kp = i / 2560;
        int k = 2 * kp + j, n = 4 * pc + c;
        float v;
        if (n < 256)      v = Wp1[n * 256 + k];
        else if (n < 512) v = Wq1[(n - 256) * 512 + k];
        else              v = Whh[(n - 512) * 256 + k];
        g_Wbig4[i] = v;
    }
    for (int i = tid; i < 128 * 64 * 4; i += nt) {
        int c = i & 1, j = (i >> 1) & 1;
        int u = (i >> 2) & 63, kp = i >> 8;
        int k = 2 * kp + j, col = 2 * (u & 31) + c;
        g_Wpq2[i] = (u < 32) ? Wp2[col * 256 + k] : Wq2[col * 256 + k];
    }
    for (int i = tid; i < 20 * 384 * 4; i += nt) {
        int c = i & 1, j = (i >> 1) & 1;
        int p = (i >> 2) % 384, kp = i / 1536;
        g_Wih2[i] = Wih[(2 * p + c) * 40 + (2 * kp + j)];
    }
    for (int i = tid; i < 64 * 256; i += nt) {
        int k = i / 256, n = i % 256;
        g_We1[i] = We1[n * 64 + k];
    }
    for (int i = tid; i < 256 * 256; i += nt) {
        int k = i / 256, n = i % 256;
        g_We2[i]  = We2[n * 256 + k];
        g_Wq1e[i] = Wq1[n * 512 + 256 + k];
    }
}

// ---------------------------------------------------------------------------
// emb: 4096 CTAs x 32 rows, 512 threads
// ---------------------------------------------------------------------------
#define EMB_T 512
#define EMB_SMEM ((32*64 + 2*32*256) * 8)

__device__ __forceinline__ void gemm256(u64 acc[4][2], const u64* in_dup,
                                        const float* Wg, int p, int r0)
{
    const ulonglong2* W = (const ulonglong2*)Wg;   // [k][64]
    #pragma unroll
    for (int r = 0; r < 4; r++) { acc[r][0] = 0ull; acc[r][1] = 0ull; }
    ulonglong2 wc0 = W[p], wc1 = W[64 + p], wc2 = W[128 + p], wc3 = W[192 + p];
    for (int kb = 0; kb < 256; kb += 4) {
        int nb = (kb + 4) * 64 + p;
        ulonglong2 wn0 = W[nb], wn1 = W[nb + 64], wn2 = W[nb + 128], wn3 = W[nb + 192];
        #pragma unroll
        for (int r = 0; r < 4; r++) {
            const ulonglong2* Hb = (const ulonglong2*)(in_dup + (long)(r0 + r) * 256) + (kb >> 1);
            ulonglong2 h01 = Hb[0], h23 = Hb[1];
            fma2(acc[r][0], h01.x, wc0.x); fma2(acc[r][1], h01.x, wc0.y);
            fma2(acc[r][0], h01.y, wc1.x); fma2(acc[r][1], h01.y, wc1.y);
            fma2(acc[r][0], h23.x, wc2.x); fma2(acc[r][1], h23.x, wc2.y);
            fma2(acc[r][0], h23.y, wc3.x); fma2(acc[r][1], h23.y, wc3.y);
        }
        wc0 = wn0; wc1 = wn1; wc2 = wn2; wc3 = wn3;
    }
}

__global__ void __launch_bounds__(EMB_T, 1) emb_kernel(
    const float* __restrict__ obs, const float* __restrict__ be1,
    const float* __restrict__ be2, const float* __restrict__ bq1)
{
    extern __shared__ u64 smu[];
    u64* obs2 = smu;               // 32*64
    u64* e1   = smu + 32 * 64;     // 32*256
    u64* e2   = e1 + 32 * 256;     // 32*256

    int t    = threadIdx.x;
    int row0 = blockIdx.x * 32;
    int p    = t & 63;
    int r0   = (t >> 6) * 4;

    for (int i = t; i < 32 * 64; i += EMB_T)
        obs2[i] = pk2(obs[(long)row0 * 64 + i]);

    float4 b1 = *(const float4*)&be1[4 * p];
    float4 b2 = *(const float4*)&be2[4 * p];
    float4 bq = *(const float4*)&bq1[4 * p];
    __syncthreads();

    u64 acc[4][2];

    // stage 1: K=64 obs -> e1
    {
        const ulonglong2* W = (const ulonglong2*)g_We1;
        #pragma unroll
        for (int r = 0; r < 4; r++) { acc[r][0] = 0ull; acc[r][1] = 0ull; }
        ulonglong2 wc0 = W[p], wc1 = W[64 + p], wc2 = W[128 + p], wc3 = W[192 + p];
        for (int kb = 0; kb < 64; kb += 4) {
            int nb = (kb + 4) * 64 + p;
            ulonglong2 wn0 = W[nb], wn1 = W[nb + 64], wn2 = W[nb + 128], wn3 = W[nb + 192];
            #pragma unroll
            for (int r = 0; r < 4; r++) {
                const ulonglong2* Hb = (const ulonglong2*)(obs2 + (long)(r0 + r) * 64) + (kb >> 1);
                ulonglong2 h01 = Hb[0], h23 = Hb[1];
                fma2(acc[r][0], h01.x, wc0.x); fma2(acc[r][1], h01.x, wc0.y);
                fma2(acc[r][0], h01.y, wc1.x); fma2(acc[r][1], h01.y, wc1.y);
                fma2(acc[r][0], h23.x, wc2.x); fma2(acc[r][1], h23.x, wc2.y);
                fma2(acc[r][0], h23.y, wc3.x); fma2(acc[r][1], h23.y, wc3.y);
            }
            wc0 = wn0; wc1 = wn1; wc2 = wn2; wc3 = wn3;
        }
        #pragma unroll
        for (int r = 0; r < 4; r++) {
            float2 a0 = upk(acc[r][0]), a1 = upk(acc[r][1]);
            ulonglong2* E = (ulonglong2*)(e1 + (long)(r0 + r) * 256 + 4 * p);
            E[0] = make_ulonglong2(pk2(eluf(a0.x + b1.x)), pk2(eluf(a0.y + b1.y)));
            E[1] = make_ulonglong2(pk2(eluf(a1.x + b1.z)), pk2(eluf(a1.y + b1.w)));
        }
    }
    __syncthreads();

    gemm256(acc, e1, g_We2, p, r0);
    #pragma unroll
    for (int r = 0; r < 4; r++) {
        float2 a0 = upk(acc[r][0]), a1 = upk(acc[r][1]);
        ulonglong2* E = (ulonglong2*)(e2 + (long)(r0 + r) * 256 + 4 * p);
        E[0] = make_ulonglong2(pk2(eluf(a0.x + b2.x)), pk2(eluf(a0.y + b2.y)));
        E[1] = make_ulonglong2(pk2(eluf(a1.x + b2.z)), pk2(eluf(a1.y + b2.w)));
    }
    __syncthreads();

    gemm256(acc, e2, g_Wq1e, p, r0);
    #pragma unroll
    for (int r = 0; r < 4; r++) {
        float2 a0 = upk(acc[r][0]), a1 = upk(acc[r][1]);
        *(float4*)&g_q1emb[(long)(row0 + r0 + r) * 256 + 4 * p] =
            make_float4(a0.x + bq.x, a0.y + bq.y, a1.x + bq.z, a1.y + bq.w);
    }
}

// ---------------------------------------------------------------------------
// seq: 128 CTAs x 8 rows, 640 threads.
// S1: warp-interleaved row split: g=(warp&1) -> rows 4g..4g+3,
//     pc=(warp>>1)*32+lane -> cols 4pc..4pc+3. Two groups read identical
//     weight lines close in time -> L1 hits halve L2 traffic.
// ---------------------------------------------------------------------------
#define SQ_T 640
#define SEQ_SMEM (10560*8 + (6144+6144)*4 + 2*2048*4)

__global__ void __launch_bounds__(SQ_T, 1) seq_kernel(
    const float* __restrict__ act,  const float* __restrict__ noise,
    const float* __restrict__ b_p1, const float* __restrict__ b_hh,
    const float* __restrict__ b_p2, const float* __restrict__ b_q2,
    const float* __restrict__ b_ih, float* __restrict__ out)
{
    extern __shared__ u64 smu[];
    u64* h2   = smu;             // [2048] dup h
    u64* G1p  = smu + 2048;      // [2048] dup elu(prior hidden)
    u64* G1q  = smu + 4096;      // [2048] dup elu(post hidden)
    u64* x2   = smu + 6144;      // [320]  dup [z|a]
    u64* part = smu + 6464;      // [4096] S2 partials [kb][r][u]
    float* Gh = (float*)(smu + 10560);  // [6144]
    float* gi = Gh + 6144;              // [6144]
    float* qb = gi + 6144;              // [2][2048] q1emb double buffer
    float* hF = (float*)h2;             // h value = hF[2*i]

    int p    = threadIdx.x;
    int b0   = blockIdx.x * 8;
    int warp = p >> 5, lane = p & 31;
    int g    = warp & 1;                 // row group
    int r4   = 4 * g;                    // first row of group
    int pc   = (warp >> 1) * 32 + lane;  // col quad 0..319
    int n0   = 4 * pc;

    for (int i = p; i < 2048; i += SQ_T) h2[i] = 0ull;
    // initial q1emb buffer (t=0) into qb[0]
    if (p < 512) {
        int r = p >> 6, c4 = (p & 63) * 4;
        *(float4*)&qb[r * 256 + c4] =
            *(const float4*)&g_q1emb[(long)(b0 + r) * Tn * 256 + c4];
    }

    // hoisted per-thread constants
    float4 bias1 = make_float4(0.f, 0.f, 0.f, 0.f);
    if (n0 < 256)       bias1 = *(const float4*)&b_p1[n0];
    else if (n0 >= 512) bias1 = *(const float4*)&b_hh[n0 - 512];
    float2 bih = make_float2(0.f, 0.f);
    if (p < 384) bih = *(const float2*)&b_ih[2 * p];

    int s2_u = p & 63, s2_kb = p >> 6;   // valid for p<512
    int s2_c = s2_u & 31;
    float2 s2_b = make_float2(0.f, 0.f);
    if (p < 512) s2_b = (s2_u < 32) ? *(const float2*)&b_p2[2 * s2_c]
                                    : *(const float2*)&b_q2[2 * s2_c];
    __syncthreads();

    const ulonglong2* W4  = (const ulonglong2*)g_Wbig4;   // 2 per (kp,pc)
    const ulonglong2* WPQ = (const ulonglong2*)g_Wpq2;    // [kp][64]
    const ulonglong2* WI  = (const ulonglong2*)g_Wih2;    // [kp][384]
    const ulonglong2* H2v = (const ulonglong2*)h2;        // [r][128]
    const ulonglong2* X2v = (const ulonglong2*)x2;        // [r][20]

    for (int tt = 0; tt < Tn; tt++) {
        const float* qcur = qb + (tt & 1) * 2048;
        float*       qnxt = qb + ((tt + 1) & 1) * 2048;

        // ================= S1: G1 = h @ [Wp1|Wq1h|Whh] =================
        u64 aA[4], aB[4];
        #pragma unroll
        for (int r = 0; r < 4; r++) { aA[r] = 0ull; aB[r] = 0ull; }
        {
            int base = pc * 2;
            ulonglong2 c00 = W4[base],       c01 = W4[base + 1];
            ulonglong2 c10 = W4[base + 640], c11 = W4[base + 641];
            for (int kp = 0; kp < 128; kp += 2) {
                int nb = (kp + 2) * 640 + base;
                ulonglong2 m00 = W4[nb],       m01 = W4[nb + 1];
                ulonglong2 m10 = W4[nb + 640], m11 = W4[nb + 641];
                #pragma unroll
                for (int r = 0; r < 4; r++) {
                    ulonglong2 h0 = H2v[(r4 + r) * 128 + kp];
                    ulonglong2 h1 = H2v[(r4 + r) * 128 + kp + 1];
                    fma2(aA[r], h0.x, c00.x); fma2(aB[r], h0.x, c00.y);
                    fma2(aA[r], h0.y, c01.x); fma2(aB[r], h0.y, c01.y);
                    fma2(aA[r], h1.x, c10.x); fma2(aB[r], h1.x, c10.y);
                    fma2(aA[r], h1.y, c11.x); fma2(aB[r], h1.y, c11.y);
                }
                c00 = m00; c01 = m01; c10 = m10; c11 = m11;
            }
        }
        if (n0 < 256) {
            #pragma unroll
            for (int r = 0; r < 4; r++) {
                float2 a0 = upk(aA[r]), a1 = upk(aB[r]);
                ulonglong2* E = (ulonglong2*)(G1p + (r4 + r) * 256 + n0);
                E[0] = make_ulonglong2(pk2(eluf(a0.x + bias1.x)), pk2(eluf(a0.y + bias1.y)));
                E[1] = make_ulonglong2(pk2(eluf(a1.x + bias1.z)), pk2(eluf(a1.y + bias1.w)));
            }
        } else if (n0 < 512) {
            #pragma unroll
            for (int r = 0; r < 4; r++) {
                float4 q = *(const float4*)&qcur[(r4 + r) * 256 + (n0 - 256)];
                float2 a0 = upk(aA[r]), a1 = upk(aB[r]);
                ulonglong2* E = (ulonglong2*)(G1q + (r4 + r) * 256 + (n0 - 256));
                E[0] = make_ulonglong2(pk2(eluf(a0.x + q.x)), pk2(eluf(a0.y + q.y)));
                E[1] = make_ulonglong2(pk2(eluf(a1.x + q.z)), pk2(eluf(a1.y + q.w)));
            }
        } else {
            #pragma unroll
            for (int r = 0; r < 4; r++) {
                float2 a0 = upk(aA[r]), a1 = upk(aB[r]);
                *(float4*)&Gh[(r4 + r) * 768 + (n0 - 512)] =
                    make_float4(a0.x + bias1.x, a0.y + bias1.y, a1.x + bias1.z, a1.y + bias1.w);
            }
        }
        __syncthreads();

        // ========== S2 partials (p<512); p>=512: h-out + q1emb prefetch ==========
        float2 eps = make_float2(0.f, 0.f);
        float  av  = 0.f;
        if (p < 512) {
            if (s2_u >= 32 && s2_u < 48) {   // z-lanes: prefetch noise
                int r = p >> 6, c = s2_u - 32;
                eps = *(const float2*)&noise[((long)tt * Bsz + b0 + r) * 32 + 2 * c];
            }
            const ulonglong2* INv = (const ulonglong2*)((s2_u < 32) ? G1p : G1q);
            u64 a8[8];
            #pragma unroll
            for (int r = 0; r < 8; r++) a8[r] = 0ull;
            int kbase = s2_kb * 16;
            #pragma unroll 4
            for (int q = 0; q < 16; q++) {
                int kpg = kbase + q;
                ulonglong2 w = WPQ[kpg * 64 + s2_u];
                #pragma unroll
                for (int r = 0; r < 8; r++) {
                    ulonglong2 iv = INv[r * 128 + kpg];
                    fma2(a8[r], iv.x, w.x);
                    fma2(a8[r], iv.y, w.y);
                }
            }
            #pragma unroll
            for (int r = 0; r < 8; r++)
                part[(s2_kb * 8 + r) * 64 + s2_u] = a8[r];
        } else {
            int idx = p - 512;   // 0..127
            if (idx < 64) {      // act prefetch
                int r = idx >> 3, j = idx & 7;
                av = act[(long)(b0 + r) * 1024 + tt * 8 + j];
            }
            #pragma unroll
            for (int j = 0; j < 16; j++) {
                int i = idx + j * 128, r = i >> 8, d = i & 255;
                out[(long)(b0 + r) * 53248 + tt * 416 + d] = hF[2 * i];
            }
            if (tt + 1 < Tn) {   // prefetch next q1emb into other buffer
                #pragma unroll
                for (int j = 0; j < 4; j++) {
                    int i = idx + j * 128;          // 0..511 float4 chunks
                    int r = i >> 6, c4 = (i & 63) * 4;
                    *(float4*)&qnxt[r * 256 + c4] =
                        *(const float4*)&g_q1emb[((long)(b0 + r) * Tn + tt + 1) * 256 + c4];
                }
            }
        }
        __syncthreads();

        // ===== S2 reduce + stats out + z (shuffle qm<->qs) + act staging =====
        if (p < 512) {
            int r = p >> 6;
            u64 s = part[r * 64 + s2_u];
            #pragma unroll
            for (int kb = 1; kb < 8; kb++)
                s = add2(s, part[(kb * 8 + r) * 64 + s2_u]);
            float2 v = upk(s);
            v.x += s2_b.x; v.y += s2_b.y;
            if (s2_c >= 16) { v.x = __expf(clipf(v.x)); v.y = __expf(clipf(v.y)); }
            // direct stats out: offset 288 + (q?64:0) + 2c covers mean/std halves
            *(float2*)&out[(long)(b0 + r) * 53248 + tt * 416 + 288 +
                           (s2_u < 32 ? 0 : 64) + 2 * s2_c] = v;
            if (s2_u >= 32) {                // Q-warps: swap qm/qs across half-warps
                float ox = __shfl_xor_sync(0xffffffffu, v.x, 16);
                float oy = __shfl_xor_sync(0xffffffffu, v.y, 16);
                if (s2_u < 48) {             // qm lanes compute z
                    int c = s2_u - 32;
                    float z0 = fmaf(ox, eps.x, v.x);
                    float z1 = fmaf(oy, eps.y, v.y);
                    *(ulonglong2*)&x2[r * 40 + 2 * c] =
                        make_ulonglong2(pk2(z0), pk2(z1));
                    *(float2*)&out[(long)(b0 + r) * 53248 + tt * 416 + 256 + 2 * c] =
                        make_float2(z0, z1);
                }
            }
        } else if (p < 576) {
            int idx = p - 512, r = idx >> 3, j = idx & 7;
            x2[r * 40 + 32 + j] = pk2(av);
        }
        __syncthreads();

        // ================= S3: gi = x @ W_ih (p<384) =================
        if (p < 384) {
            u64 a3[8];
            #pragma unroll
            for (int r = 0; r < 8; r++) a3[r] = 0ull;
            #pragma unroll 4
            for (int kp = 0; kp < 20; kp++) {
                ulonglong2 w = WI[kp * 384 + p];
                #pragma unroll
                for (int r = 0; r < 8; r++) {
                    ulonglong2 iv = X2v[r * 20 + kp];
                    fma2(a3[r], iv.x, w.x);
                    fma2(a3[r], iv.y, w.y);
                }
            }
            #pragma unroll
            for (int r = 0; r < 8; r++) {
                float2 a0 = upk(a3[r]);
                *(float2*)&gi[r * 768 + 2 * p] = make_float2(a0.x + bih.x, a0.y + bih.y);
            }
        }
        __syncthreads();

        // ================= S4: GRU gates -> new h =================
        for (int i = p; i < 2048; i += SQ_T) {
            int r = i >> 8, d = i & 255;
            float gir = gi[r * 768 + d];
            float giz = gi[r * 768 + 256 + d];
            float gin = gi[r * 768 + 512 + d];
            float ghr = Gh[r * 768 + d];
            float ghz = Gh[r * 768 + 256 + d];
            float ghn = Gh[r * 768 + 512 + d];
            float rg = sigf(gir + ghr);
            float ug = sigf(giz + ghz);
            float ng = tanf_(gin + rg * ghn);
            float ho = hF[2 * i];
            h2[i] = pk2((1.f - ug) * ng + ug * ho);
        }
        __syncthreads();
    }
}

// ---------------------------------------------------------------------------
extern "C" void kernel_launch(void* const* d_in, const int* in_sizes, int n_in,
                              void* d_out, int out_size)
{
    const float* obs = (const float*)d_in[0];
    const float* act = (const float*)d_in[1];
    const float* noi = (const float*)d_in[2];
    const float* We1 = (const float*)d_in[3];
    const float* be1 = (const float*)d_in[4];
    const float* We2 = (const float*)d_in[5];
    const float* be2 = (const float*)d_in[6];
    const float* Wih = (const float*)d_in[7];
    const float* Whh = (const float*)d_in[8];
    const float* bih = (const float*)d_in[9];
    const float* bhh = (const float*)d_in[10];
    const float* Wp1 = (const float*)d_in[11];
    const float* bp1 = (const float*)d_in[12];
    const float* Wp2 = (const float*)d_in[13];
    const float* bp2 = (const float*)d_in[14];
    const float* Wq1 = (const float*)d_in[15];
    const float* bq1 = (const float*)d_in[16];
    const float* Wq2 = (const float*)d_in[17];
    const float* bq2 = (const float*)d_in[18];
    float* out = (float*)d_out;

    cudaFuncSetAttribute(emb_kernel, cudaFuncAttributeMaxDynamicSharedMemorySize, EMB_SMEM);
    cudaFuncSetAttribute(seq_kernel, cudaFuncAttributeMaxDynamicSharedMemorySize, SEQ_SMEM);

    prep_kernel<<<64, 256>>>(Wp1, Wq1, Whh, Wih, Wp2, Wq2, We1, We2);
    emb_kernel<<<(Bsz * Tn) / 32, EMB_T, EMB_SMEM>>>(obs, be1, be2, bq1);
    seq_kernel<<<Bsz / 8, SQ_T, SEQ_SMEM>>>(act, noi, bp1, bhh, bp2, bq2, bih, out);
}

// round 6
// speedup vs baseline: 1.1168x; 1.1168x over previous
#include <cuda_runtime.h>

typedef unsigned long long u64;

#define Bsz 1024
#define Tn  128

__device__ __forceinline__ void fma2(u64 &d, u64 a, u64 b) {
    asm("fma.rn.f32x2 %0, %1, %2, %0;" : "+l"(d) : "l"(a), "l"(b));
}
__device__ __forceinline__ u64 add2(u64 a, u64 b) {
    u64 r; asm("add.rn.f32x2 %0, %1, %2;" : "=l"(r) : "l"(a), "l"(b)); return r;
}
__device__ __forceinline__ u64 pk2(float x) {
    u64 r; unsigned xi = __float_as_uint(x);
    asm("mov.b64 %0, {%1, %2};" : "=l"(r) : "r"(xi), "r"(xi));
    return r;
}
__device__ __forceinline__ float2 upk(u64 v) {
    unsigned lo, hi;
    asm("mov.b64 {%0, %1}, %2;" : "=r"(lo), "=r"(hi) : "l"(v));
    return make_float2(__uint_as_float(lo), __uint_as_float(hi));
}
// fast-math activations (validated R5: rel_err 1.5e-7, tolerance 1e-3)
__device__ __forceinline__ float eluf(float x)  { return x > 0.f ? x : (__expf(x) - 1.f); }
__device__ __forceinline__ float sigf(float x)  { return __fdividef(1.f, 1.f + __expf(-x)); }
__device__ __forceinline__ float tanf_(float x) {
    x = fminf(fmaxf(x, -20.f), 20.f);
    float t = __expf(2.f * x);
    return __fdividef(t - 1.f, t + 1.f);
}
__device__ __forceinline__ float clipf(float x) { return fminf(fmaxf(x, -7.f), 5.f); }

// ---- weight scratch (zero-init; padded for prefetch overrun) --------------
// Wbig2: [kp][p(640)][4]: [2j+c] = Wfused[2kp+j][2p+c]; kp<128 (pad 132)
__device__ float g_Wbig2[132 * 640 * 4];
// Wpq2: [kp][u(64)][4]: [2j+c] = Wstats[2(u&31)+c][2kp+j] (u<32 P, else Q)
__device__ float g_Wpq2 [128 * 64 * 4];
// Wih2: [kp][p(384)][4]
__device__ float g_Wih2 [20 * 384 * 4];
// emb weights [k][n], padded rows
__device__ float g_We1  [72 * 256];
__device__ float g_We2  [264 * 256];
__device__ float g_Wq1e [264 * 256];
__device__ float g_q1emb[(long)Bsz * Tn * 256];

// ---------------------------------------------------------------------------
__global__ void prep_kernel(const float* __restrict__ Wp1, const float* __restrict__ Wq1,
                            const float* __restrict__ Whh, const float* __restrict__ Wih,
                            const float* __restrict__ Wp2, const float* __restrict__ Wq2,
                            const float* __restrict__ We1, const float* __restrict__ We2)
{
    int tid = blockIdx.x * blockDim.x + threadIdx.x;
    int nt  = gridDim.x * blockDim.x;
    for (int i = tid; i < 128 * 640 * 4; i += nt) {
        int c = i & 1, j = (i >> 1) & 1;
        int p = (i >> 2) % 640, kp = i / 2560;
        int k = 2 * kp + j, n = 2 * p + c;
        float v;
        if (n < 256)      v = Wp1[n * 256 + k];
        else if (n < 512) v = Wq1[(n - 256) * 512 + k];
        else              v = Whh[(n - 512) * 256 + k];
        g_Wbig2[i] = v;
    }
    for (int i = tid; i < 128 * 64 * 4; i += nt) {
        int c = i & 1, j = (i >> 1) & 1;
        int u = (i >> 2) & 63, kp = i >> 8;
        int k = 2 * kp + j, col = 2 * (u & 31) + c;
        g_Wpq2[i] = (u < 32) ? Wp2[col * 256 + k] : Wq2[col * 256 + k];
    }
    for (int i = tid; i < 20 * 384 * 4; i += nt) {
        int c = i & 1, j = (i >> 1) & 1;
        int p = (i >> 2) % 384, kp = i / 1536;
        g_Wih2[i] = Wih[(2 * p + c) * 40 + (2 * kp + j)];
    }
    for (int i = tid; i < 64 * 256; i += nt) {
        int k = i / 256, n = i % 256;
        g_We1[i] = We1[n * 64 + k];
    }
    for (int i = tid; i < 256 * 256; i += nt) {
        int k = i / 256, n = i % 256;
        g_We2[i]  = We2[n * 256 + k];
        g_Wq1e[i] = Wq1[n * 512 + 256 + k];
    }
}

// ---------------------------------------------------------------------------
// emb: 4096 CTAs x 32 rows, 512 threads
// ---------------------------------------------------------------------------
#define EMB_T 512
#define EMB_SMEM ((32*64 + 2*32*256) * 8)

__device__ __forceinline__ void gemm256(u64 acc[4][2], const u64* in_dup,
                                        const float* Wg, int p, int r0)
{
    const ulonglong2* W = (const ulonglong2*)Wg;   // [k][64]
    #pragma unroll
    for (int r = 0; r < 4; r++) { acc[r][0] = 0ull; acc[r][1] = 0ull; }
    ulonglong2 wc0 = W[p], wc1 = W[64 + p], wc2 = W[128 + p], wc3 = W[192 + p];
    for (int kb = 0; kb < 256; kb += 4) {
        int nb = (kb + 4) * 64 + p;
        ulonglong2 wn0 = W[nb], wn1 = W[nb + 64], wn2 = W[nb + 128], wn3 = W[nb + 192];
        #pragma unroll
        for (int r = 0; r < 4; r++) {
            const ulonglong2* Hb = (const ulonglong2*)(in_dup + (long)(r0 + r) * 256) + (kb >> 1);
            ulonglong2 h01 = Hb[0], h23 = Hb[1];
            fma2(acc[r][0], h01.x, wc0.x); fma2(acc[r][1], h01.x, wc0.y);
            fma2(acc[r][0], h01.y, wc1.x); fma2(acc[r][1], h01.y, wc1.y);
            fma2(acc[r][0], h23.x, wc2.x); fma2(acc[r][1], h23.x, wc2.y);
            fma2(acc[r][0], h23.y, wc3.x); fma2(acc[r][1], h23.y, wc3.y);
        }
        wc0 = wn0; wc1 = wn1; wc2 = wn2; wc3 = wn3;
    }
}

__global__ void __launch_bounds__(EMB_T, 1) emb_kernel(
    const float* __restrict__ obs, const float* __restrict__ be1,
    const float* __restrict__ be2, const float* __restrict__ bq1)
{
    extern __shared__ u64 smu[];
    u64* obs2 = smu;               // 32*64
    u64* e1   = smu + 32 * 64;     // 32*256
    u64* e2   = e1 + 32 * 256;     // 32*256

    int t    = threadIdx.x;
    int row0 = blockIdx.x * 32;
    int p    = t & 63;
    int r0   = (t >> 6) * 4;

    for (int i = t; i < 32 * 64; i += EMB_T)
        obs2[i] = pk2(__ldcs(&obs[(long)row0 * 64 + i]));

    float4 b1 = *(const float4*)&be1[4 * p];
    float4 b2 = *(const float4*)&be2[4 * p];
    float4 bq = *(const float4*)&bq1[4 * p];
    __syncthreads();

    u64 acc[4][2];

    // stage 1: K=64 obs -> e1
    {
        const ulonglong2* W = (const ulonglong2*)g_We1;
        #pragma unroll
        for (int r = 0; r < 4; r++) { acc[r][0] = 0ull; acc[r][1] = 0ull; }
        ulonglong2 wc0 = W[p], wc1 = W[64 + p], wc2 = W[128 + p], wc3 = W[192 + p];
        for (int kb = 0; kb < 64; kb += 4) {
            int nb = (kb + 4) * 64 + p;
            ulonglong2 wn0 = W[nb], wn1 = W[nb + 64], wn2 = W[nb + 128], wn3 = W[nb + 192];
            #pragma unroll
            for (int r = 0; r < 4; r++) {
                const ulonglong2* Hb = (const ulonglong2*)(obs2 + (long)(r0 + r) * 64) + (kb >> 1);
                ulonglong2 h01 = Hb[0], h23 = Hb[1];
                fma2(acc[r][0], h01.x, wc0.x); fma2(acc[r][1], h01.x, wc0.y);
                fma2(acc[r][0], h01.y, wc1.x); fma2(acc[r][1], h01.y, wc1.y);
                fma2(acc[r][0], h23.x, wc2.x); fma2(acc[r][1], h23.x, wc2.y);
                fma2(acc[r][0], h23.y, wc3.x); fma2(acc[r][1], h23.y, wc3.y);
            }
            wc0 = wn0; wc1 = wn1; wc2 = wn2; wc3 = wn3;
        }
        #pragma unroll
        for (int r = 0; r < 4; r++) {
            float2 a0 = upk(acc[r][0]), a1 = upk(acc[r][1]);
            ulonglong2* E = (ulonglong2*)(e1 + (long)(r0 + r) * 256 + 4 * p);
            E[0] = make_ulonglong2(pk2(eluf(a0.x + b1.x)), pk2(eluf(a0.y + b1.y)));
            E[1] = make_ulonglong2(pk2(eluf(a1.x + b1.z)), pk2(eluf(a1.y + b1.w)));
        }
    }
    __syncthreads();

    gemm256(acc, e1, g_We2, p, r0);
    #pragma unroll
    for (int r = 0; r < 4; r++) {
        float2 a0 = upk(acc[r][0]), a1 = upk(acc[r][1]);
        ulonglong2* E = (ulonglong2*)(e2 + (long)(r0 + r) * 256 + 4 * p);
        E[0] = make_ulonglong2(pk2(eluf(a0.x + b2.x)), pk2(eluf(a0.y + b2.y)));
        E[1] = make_ulonglong2(pk2(eluf(a1.x + b2.z)), pk2(eluf(a1.y + b2.w)));
    }
    __syncthreads();

    gemm256(acc, e2, g_Wq1e, p, r0);
    #pragma unroll
    for (int r = 0; r < 4; r++) {
        float2 a0 = upk(acc[r][0]), a1 = upk(acc[r][1]);
        float4 v = make_float4(a0.x + bq.x, a0.y + bq.y, a1.x + bq.z, a1.y + bq.w);
        __stcs((float4*)&g_q1emb[(long)(row0 + r0 + r) * 256 + 4 * p], v);
    }
}

// ---------------------------------------------------------------------------
// seq: 128 CTAs x 8 rows, 640 threads (thread p owns cols 2p, 2p+1)
// R4 structure + qb double-buffer prefetch + fast-math + streaming hints
// ---------------------------------------------------------------------------
#define SQ_T 640
#define SEQ_SMEM (10560*8 + (6144 + 6144 + 1024 + 4096)*4)

__global__ void __launch_bounds__(SQ_T, 1) seq_kernel(
    const float* __restrict__ act,  const float* __restrict__ noise,
    const float* __restrict__ b_p1, const float* __restrict__ b_hh,
    const float* __restrict__ b_p2, const float* __restrict__ b_q2,
    const float* __restrict__ b_ih, float* __restrict__ out)
{
    extern __shared__ u64 smu[];
    u64* h2   = smu;             // [2048] dup h
    u64* G1p  = smu + 2048;      // [2048] dup elu(prior hidden)
    u64* G1q  = smu + 4096;      // [2048] dup elu(post hidden)
    u64* x2   = smu + 6144;      // [320]  dup [z|a]
    u64* part = smu + 6464;      // [4096] S2 partials [kb][r][u]
    float* Gh = (float*)(smu + 10560);  // [6144]
    float* gi = Gh + 6144;              // [6144]
    float* pq = gi + 6144;              // [1024] pm|ps|qm|qs
    float* qb = pq + 1024;              // [2][2048] q1emb double buffer
    float* hF = (float*)h2;             // h value = hF[2*i]

    int p  = threadIdx.x;
    int b0 = blockIdx.x * 8;
    int n0 = 2 * p;

    for (int i = p; i < 2048; i += SQ_T) h2[i] = 0ull;
    // initial q1emb buffer (t=0) into qb[0]
    if (p < 512) {
        int r = p >> 6, c4 = (p & 63) * 4;
        *(float4*)&qb[r * 256 + c4] =
            __ldcs((const float4*)&g_q1emb[(long)(b0 + r) * Tn * 256 + c4]);
    }

    // hoisted per-thread constants
    float2 bias1 = make_float2(0.f, 0.f);
    if (n0 < 256)       bias1 = *(const float2*)&b_p1[n0];
    else if (n0 >= 512) bias1 = *(const float2*)&b_hh[n0 - 512];
    float2 bih = make_float2(0.f, 0.f);
    if (p < 384) bih = *(const float2*)&b_ih[n0];

    int s2_u = p & 63, s2_kb = p >> 6;          // valid for p<512
    int s2_c = s2_u & 31;
    float2 s2_b = make_float2(0.f, 0.f);
    if (p < 512) s2_b = (s2_u < 32) ? *(const float2*)&b_p2[2 * s2_c]
                                    : *(const float2*)&b_q2[2 * s2_c];
    __syncthreads();

    const ulonglong2* WB  = (const ulonglong2*)g_Wbig2;   // [kp][640]
    const ulonglong2* WPQ = (const ulonglong2*)g_Wpq2;    // [kp][64]
    const ulonglong2* WI  = (const ulonglong2*)g_Wih2;    // [kp][384]
    const ulonglong2* H2v = (const ulonglong2*)h2;        // [r][128]
    const ulonglong2* X2v = (const ulonglong2*)x2;        // [r][20]

    for (int tt = 0; tt < Tn; tt++) {
        const float* qcur = qb + (tt & 1) * 2048;
        float*       qnxt = qb + ((tt + 1) & 1) * 2048;

        // --- prefetch (consumed in S2.5, latency hidden under S1) ---
        float ep = 0.f, av = 0.f;
        if (p < 256) {
            int r = p >> 5, s = p & 31;
            ep = __ldcs(&noise[(long)tt * 32768 + (b0 + r) * 32 + s]);
        } else if (p < 320) {
            int q = p - 256, r = q >> 3, j = q & 7;
            av = __ldcs(&act[(long)(b0 + r) * 1024 + tt * 8 + j]);
        }

        // ================= S1: G1 = h @ [Wp1|Wq1h|Whh] =================
        u64 acc[8];
        #pragma unroll
        for (int r = 0; r < 8; r++) acc[r] = 0ull;
        {
            ulonglong2 wc0 = WB[p], wc1 = WB[640 + p];
            for (int kp2 = 0; kp2 < 128; kp2 += 2) {
                int nb = (kp2 + 2) * 640 + p;
                ulonglong2 wn0 = WB[nb], wn1 = WB[nb + 640];
                #pragma unroll
                for (int r = 0; r < 8; r++) {
                    ulonglong2 h01 = H2v[r * 128 + kp2];
                    ulonglong2 h23 = H2v[r * 128 + kp2 + 1];
                    fma2(acc[r], h01.x, wc0.x);
                    fma2(acc[r], h01.y, wc0.y);
                    fma2(acc[r], h23.x, wc1.x);
                    fma2(acc[r], h23.y, wc1.y);
                }
                wc0 = wn0; wc1 = wn1;
            }
        }
        if (n0 < 256) {
            #pragma unroll
            for (int r = 0; r < 8; r++) {
                float2 a0 = upk(acc[r]);
                *(ulonglong2*)(G1p + r * 256 + n0) =
                    make_ulonglong2(pk2(eluf(a0.x + bias1.x)), pk2(eluf(a0.y + bias1.y)));
            }
        } else if (n0 < 512) {
            #pragma unroll
            for (int r = 0; r < 8; r++) {
                float2 q = *(const float2*)&qcur[r * 256 + (n0 - 256)];
                float2 a0 = upk(acc[r]);
                *(ulonglong2*)(G1q + r * 256 + (n0 - 256)) =
                    make_ulonglong2(pk2(eluf(a0.x + q.x)), pk2(eluf(a0.y + q.y)));
            }
        } else {
            #pragma unroll
            for (int r = 0; r < 8; r++) {
                float2 a0 = upk(acc[r]);
                *(float2*)&Gh[r * 768 + (n0 - 512)] =
                    make_float2(a0.x + bias1.x, a0.y + bias1.y);
            }
        }
        __syncthreads();

        // ==== S2 partials (p<512); p>=512: h-out + next-q1emb prefetch ====
        if (p < 512) {
            const ulonglong2* INv = (const ulonglong2*)((s2_u < 32) ? G1p : G1q);
            u64 a8[8];
            #pragma unroll
            for (int r = 0; r < 8; r++) a8[r] = 0ull;
            int kbase = s2_kb * 16;
            #pragma unroll 4
            for (int q = 0; q < 16; q++) {
                int kpg = kbase + q;
                ulonglong2 w = WPQ[kpg * 64 + s2_u];
                #pragma unroll
                for (int r = 0; r < 8; r++) {
                    ulonglong2 iv = INv[r * 128 + kpg];
                    fma2(a8[r], iv.x, w.x);
                    fma2(a8[r], iv.y, w.y);
                }
            }
            #pragma unroll
            for (int r = 0; r < 8; r++)
                part[(s2_kb * 8 + r) * 64 + s2_u] = a8[r];
        } else {
            int idx = p - 512;   // 0..127
            #pragma unroll
            for (int j = 0; j < 16; j++) {
                int i = idx + j * 128, r = i >> 8, d = i & 255;
                __stcs(&out[(long)(b0 + r) * 53248 + tt * 416 + d], hF[2 * i]);
            }
            if (tt + 1 < Tn) {   // prefetch next step's q1emb into other buffer
                #pragma unroll
                for (int j = 0; j < 4; j++) {
                    int i = idx + j * 128;          // 0..511 float4 chunks
                    int r = i >> 6, c4 = (i & 63) * 4;
                    *(float4*)&qnxt[r * 256 + c4] =
                        __ldcs((const float4*)&g_q1emb[((long)(b0 + r) * Tn + tt + 1) * 256 + c4]);
                }
            }
        }
        __syncthreads();

        // ================= S2 reduce -> pq =================
        if (p < 512) {
            int r = p >> 6;
            u64 s = part[r * 64 + s2_u];
            #pragma unroll
            for (int kb = 1; kb < 8; kb++)
                s = add2(s, part[(kb * 8 + r) * 64 + s2_u]);
            float2 v = upk(s);
            v.x += s2_b.x; v.y += s2_b.y;
            if (s2_c >= 16) { v.x = __expf(clipf(v.x)); v.y = __expf(clipf(v.y)); }
            *(float2*)&pq[r * 128 + (s2_u < 32 ? 0 : 64) + 2 * s2_c] = v;
        }
        __syncthreads();

        // ========== S2.5: z + act staging; pq out on idle threads ==========
        if (p < 256) {
            int r = p >> 5, s = p & 31;
            float qm = pq[r * 128 + 64 + s], qs = pq[r * 128 + 96 + s];
            float z  = fmaf(qs, ep, qm);
            x2[r * 40 + s] = pk2(z);
            __stcs(&out[(long)(b0 + r) * 53248 + tt * 416 + 256 + s], z);
        } else if (p < 320) {
            int q = p - 256, r = q >> 3, j = q & 7;
            x2[r * 40 + 32 + j] = pk2(av);
        } else if (p < 576) {
            int i = p - 320;         // 0..255 float4 chunks of pq
            int r = i >> 5, cc = 4 * (i & 31);
            __stcs((float4*)&out[(long)(b0 + r) * 53248 + tt * 416 + 288 + cc],
                   *(const float4*)&pq[r * 128 + cc]);
        }
        __syncthreads();

        // ================= S3: gi = x @ W_ih (p<384) =================
        if (p < 384) {
            u64 a3[8];
            #pragma unroll
            for (int r = 0; r < 8; r++) a3[r] = 0ull;
            #pragma unroll 4
            for (int kp = 0; kp < 20; kp++) {
                ulonglong2 w = WI[kp * 384 + p];
                #pragma unroll
                for (int r = 0; r < 8; r++) {
                    ulonglong2 iv = X2v[r * 20 + kp];
                    fma2(a3[r], iv.x, w.x);
                    fma2(a3[r], iv.y, w.y);
                }
            }
            #pragma unroll
            for (int r = 0; r < 8; r++) {
                float2 a0 = upk(a3[r]);
                *(float2*)&gi[r * 768 + n0] = make_float2(a0.x + bih.x, a0.y + bih.y);
            }
        }
        __syncthreads();

        // ================= S4: GRU gates -> new h =================
        for (int i = p; i < 2048; i += SQ_T) {
            int r = i >> 8, d = i & 255;
            float gir = gi[r * 768 + d];
            float giz = gi[r * 768 + 256 + d];
            float gin = gi[r * 768 + 512 + d];
            float ghr = Gh[r * 768 + d];
            float ghz = Gh[r * 768 + 256 + d];
            float ghn = Gh[r * 768 + 512 + d];
            float rg = sigf(gir + ghr);
            float ug = sigf(giz + ghz);
            float ng = tanf_(gin + rg * ghn);
            float ho = hF[2 * i];
            h2[i] = pk2((1.f - ug) * ng + ug * ho);
        }
        __syncthreads();
    }
}

// ---------------------------------------------------------------------------
extern "C" void kernel_launch(void* const* d_in, const int* in_sizes, int n_in,
                              void* d_out, int out_size)
{
    const float* obs = (const float*)d_in[0];
    const float* act = (const float*)d_in[1];
    const float* noi = (const float*)d_in[2];
    const float* We1 = (const float*)d_in[3];
    const float* be1 = (const float*)d_in[4];
    const float* We2 = (const float*)d_in[5];
    const float* be2 = (const float*)d_in[6];
    const float* Wih = (const float*)d_in[7];
    const float* Whh = (const float*)d_in[8];
    const float* bih = (const float*)d_in[9];
    const float* bhh = (const float*)d_in[10];
    const float* Wp1 = (const float*)d_in[11];
    const float* bp1 = (const float*)d_in[12];
    const float* Wp2 = (const float*)d_in[13];
    const float* bp2 = (const float*)d_in[14];
    const float* Wq1 = (const float*)d_in[15];
    const float* bq1 = (const float*)d_in[16];
    const float* Wq2 = (const float*)d_in[17];
    const float* bq2 = (const float*)d_in[18];
    float* out = (float*)d_out;

    cudaFuncSetAttribute(emb_kernel, cudaFuncAttributeMaxDynamicSharedMemorySize, EMB_SMEM);
    cudaFuncSetAttribute(seq_kernel, cudaFuncAttributeMaxDynamicSharedMemorySize, SEQ_SMEM);

    prep_kernel<<<64, 256>>>(Wp1, Wq1, Whh, Wih, Wp2, Wq2, We1, We2);
    emb_kernel<<<(Bsz * Tn) / 32, EMB_T, EMB_SMEM>>>(obs, be1, be2, bq1);
    seq_kernel<<<Bsz / 8, SQ_T, SEQ_SMEM>>>(act, noi, bp1, bhh, bp2, bq2, bih, out);
}

// round 7
// speedup vs baseline: 1.2156x; 1.0884x over previous
#include <cuda_runtime.h>

typedef unsigned long long u64;

#define Bsz 1024
#define Tn  128

__device__ __forceinline__ void fma2(u64 &d, u64 a, u64 b) {
    asm("fma.rn.f32x2 %0, %1, %2, %0;" : "+l"(d) : "l"(a), "l"(b));
}
__device__ __forceinline__ u64 add2(u64 a, u64 b) {
    u64 r; asm("add.rn.f32x2 %0, %1, %2;" : "=l"(r) : "l"(a), "l"(b)); return r;
}
__device__ __forceinline__ u64 pk2(float x) {
    u64 r; unsigned xi = __float_as_uint(x);
    asm("mov.b64 %0, {%1, %2};" : "=l"(r) : "r"(xi), "r"(xi));
    return r;
}
__device__ __forceinline__ float2 upk(u64 v) {
    unsigned lo, hi;
    asm("mov.b64 {%0, %1}, %2;" : "=r"(lo), "=r"(hi) : "l"(v));
    return make_float2(__uint_as_float(lo), __uint_as_float(hi));
}
// fast-math activations (validated R5/R6: rel_err 1.5e-7, tolerance 1e-3)
__device__ __forceinline__ float eluf(float x)  { return x > 0.f ? x : (__expf(x) - 1.f); }
__device__ __forceinline__ float sigf(float x)  { return __fdividef(1.f, 1.f + __expf(-x)); }
__device__ __forceinline__ float tanf_(float x) {
    x = fminf(fmaxf(x, -20.f), 20.f);
    float t = __expf(2.f * x);
    return __fdividef(t - 1.f, t + 1.f);
}
__device__ __forceinline__ float clipf(float x) { return fminf(fmaxf(x, -7.f), 5.f); }

// ---- weight scratch (zero-init; padded for prefetch overrun) --------------
// Wbig4: [kp][q(320)][8]: [j*4+c] = Wfused[2kp+j][4q+c]; kp<128 (pad 132)
__device__ float g_Wbig4[132 * 320 * 8];
// Wpq2: [kp][u(64)][4]: [2j+c] = Wstats[2(u&31)+c][2kp+j] (u<32 P, else Q)
__device__ float g_Wpq2 [128 * 64 * 4];
// Wih2: [kp][p(384)][4]
__device__ float g_Wih2 [20 * 384 * 4];
// emb weights [k][n], padded rows
__device__ float g_We1  [72 * 256];
__device__ float g_We2  [264 * 256];
__device__ float g_Wq1e [264 * 256];
__device__ float g_q1emb[(long)Bsz * Tn * 256];

// ---------------------------------------------------------------------------
__global__ void prep_kernel(const float* __restrict__ Wp1, const float* __restrict__ Wq1,
                            const float* __restrict__ Whh, const float* __restrict__ Wih,
                            const float* __restrict__ Wp2, const float* __restrict__ Wq2,
                            const float* __restrict__ We1, const float* __restrict__ We2)
{
    int tid = blockIdx.x * blockDim.x + threadIdx.x;
    int nt  = gridDim.x * blockDim.x;
    for (int i = tid; i < 128 * 320 * 8; i += nt) {
        int c = i & 3, j = (i >> 2) & 1;
        int q = (i >> 3) % 320, kp = i / 2560;
        int k = 2 * kp + j, n = 4 * q + c;
        float v;
        if (n < 256)      v = Wp1[n * 256 + k];
        else if (n < 512) v = Wq1[(n - 256) * 512 + k];
        else              v = Whh[(n - 512) * 256 + k];
        g_Wbig4[i] = v;
    }
    for (int i = tid; i < 128 * 64 * 4; i += nt) {
        int c = i & 1, j = (i >> 1) & 1;
        int u = (i >> 2) & 63, kp = i >> 8;
        int k = 2 * kp + j, col = 2 * (u & 31) + c;
        g_Wpq2[i] = (u < 32) ? Wp2[col * 256 + k] : Wq2[col * 256 + k];
    }
    for (int i = tid; i < 20 * 384 * 4; i += nt) {
        int c = i & 1, j = (i >> 1) & 1;
        int p = (i >> 2) % 384, kp = i / 1536;
        g_Wih2[i] = Wih[(2 * p + c) * 40 + (2 * kp + j)];
    }
    for (int i = tid; i < 64 * 256; i += nt) {
        int k = i / 256, n = i % 256;
        g_We1[i] = We1[n * 64 + k];
    }
    for (int i = tid; i < 256 * 256; i += nt) {
        int k = i / 256, n = i % 256;
        g_We2[i]  = We2[n * 256 + k];
        g_Wq1e[i] = Wq1[n * 512 + 256 + k];
    }
}

// ---------------------------------------------------------------------------
// emb: 4096 CTAs x 32 rows, 512 threads (unchanged from R6)
// ---------------------------------------------------------------------------
#define EMB_T 512
#define EMB_SMEM ((32*64 + 2*32*256) * 8)

__device__ __forceinline__ void gemm256(u64 acc[4][2], const u64* in_dup,
                                        const float* Wg, int p, int r0)
{
    const ulonglong2* W = (const ulonglong2*)Wg;   // [k][64]
    #pragma unroll
    for (int r = 0; r < 4; r++) { acc[r][0] = 0ull; acc[r][1] = 0ull; }
    ulonglong2 wc0 = W[p], wc1 = W[64 + p], wc2 = W[128 + p], wc3 = W[192 + p];
    for (int kb = 0; kb < 256; kb += 4) {
        int nb = (kb + 4) * 64 + p;
        ulonglong2 wn0 = W[nb], wn1 = W[nb + 64], wn2 = W[nb + 128], wn3 = W[nb + 192];
        #pragma unroll
        for (int r = 0; r < 4; r++) {
            const ulonglong2* Hb = (const ulonglong2*)(in_dup + (long)(r0 + r) * 256) + (kb >> 1);
            ulonglong2 h01 = Hb[0], h23 = Hb[1];
            fma2(acc[r][0], h01.x, wc0.x); fma2(acc[r][1], h01.x, wc0.y);
            fma2(acc[r][0], h01.y, wc1.x); fma2(acc[r][1], h01.y, wc1.y);
            fma2(acc[r][0], h23.x, wc2.x); fma2(acc[r][1], h23.x, wc2.y);
            fma2(acc[r][0], h23.y, wc3.x); fma2(acc[r][1], h23.y, wc3.y);
        }
        wc0 = wn0; wc1 = wn1; wc2 = wn2; wc3 = wn3;
    }
}

__global__ void __launch_bounds__(EMB_T, 1) emb_kernel(
    const float* __restrict__ obs, const float* __restrict__ be1,
    const float* __restrict__ be2, const float* __restrict__ bq1)
{
    extern __shared__ u64 smu[];
    u64* obs2 = smu;               // 32*64
    u64* e1   = smu + 32 * 64;     // 32*256
    u64* e2   = e1 + 32 * 256;     // 32*256

    int t    = threadIdx.x;
    int row0 = blockIdx.x * 32;
    int p    = t & 63;
    int r0   = (t >> 6) * 4;

    for (int i = t; i < 32 * 64; i += EMB_T)
        obs2[i] = pk2(__ldcs(&obs[(long)row0 * 64 + i]));

    float4 b1 = *(const float4*)&be1[4 * p];
    float4 b2 = *(const float4*)&be2[4 * p];
    float4 bq = *(const float4*)&bq1[4 * p];
    __syncthreads();

    u64 acc[4][2];

    // stage 1: K=64 obs -> e1
    {
        const ulonglong2* W = (const ulonglong2*)g_We1;
        #pragma unroll
        for (int r = 0; r < 4; r++) { acc[r][0] = 0ull; acc[r][1] = 0ull; }
        ulonglong2 wc0 = W[p], wc1 = W[64 + p], wc2 = W[128 + p], wc3 = W[192 + p];
        for (int kb = 0; kb < 64; kb += 4) {
            int nb = (kb + 4) * 64 + p;
            ulonglong2 wn0 = W[nb], wn1 = W[nb + 64], wn2 = W[nb + 128], wn3 = W[nb + 192];
            #pragma unroll
            for (int r = 0; r < 4; r++) {
                const ulonglong2* Hb = (const ulonglong2*)(obs2 + (long)(r0 + r) * 64) + (kb >> 1);
                ulonglong2 h01 = Hb[0], h23 = Hb[1];
                fma2(acc[r][0], h01.x, wc0.x); fma2(acc[r][1], h01.x, wc0.y);
                fma2(acc[r][0], h01.y, wc1.x); fma2(acc[r][1], h01.y, wc1.y);
                fma2(acc[r][0], h23.x, wc2.x); fma2(acc[r][1], h23.x, wc2.y);
                fma2(acc[r][0], h23.y, wc3.x); fma2(acc[r][1], h23.y, wc3.y);
            }
            wc0 = wn0; wc1 = wn1; wc2 = wn2; wc3 = wn3;
        }
        #pragma unroll
        for (int r = 0; r < 4; r++) {
            float2 a0 = upk(acc[r][0]), a1 = upk(acc[r][1]);
            ulonglong2* E = (ulonglong2*)(e1 + (long)(r0 + r) * 256 + 4 * p);
            E[0] = make_ulonglong2(pk2(eluf(a0.x + b1.x)), pk2(eluf(a0.y + b1.y)));
            E[1] = make_ulonglong2(pk2(eluf(a1.x + b1.z)), pk2(eluf(a1.y + b1.w)));
        }
    }
    __syncthreads();

    gemm256(acc, e1, g_We2, p, r0);
    #pragma unroll
    for (int r = 0; r < 4; r++) {
        float2 a0 = upk(acc[r][0]), a1 = upk(acc[r][1]);
        ulonglong2* E = (ulonglong2*)(e2 + (long)(r0 + r) * 256 + 4 * p);
        E[0] = make_ulonglong2(pk2(eluf(a0.x + b2.x)), pk2(eluf(a0.y + b2.y)));
        E[1] = make_ulonglong2(pk2(eluf(a1.x + b2.z)), pk2(eluf(a1.y + b2.w)));
    }
    __syncthreads();

    gemm256(acc, e2, g_Wq1e, p, r0);
    #pragma unroll
    for (int r = 0; r < 4; r++) {
        float2 a0 = upk(acc[r][0]), a1 = upk(acc[r][1]);
        float4 v = make_float4(a0.x + bq.x, a0.y + bq.y, a1.x + bq.z, a1.y + bq.w);
        __stcs((float4*)&g_q1emb[(long)(row0 + r0 + r) * 256 + 4 * p], v);
    }
}

// ---------------------------------------------------------------------------
// seq: 128 CTAs x 8 rows, 640 threads.
// S1 k-split: half A (p<320) k 0..127, half B (p>=320) k 128..255; each
// thread: 4 cols x 8 rows over its k-half. Cross-half reduce via smem.
// A epilogues rows 0-3, B rows 4-7. Halves LDS wavefronts, doubles LDG MLP;
// weights still read exactly once per CTA.
// ---------------------------------------------------------------------------
#define SQ_T 640
#define SEQ_SMEM (11584*8 + (6144 + 6144 + 1024 + 4096)*4)

__global__ void __launch_bounds__(SQ_T, 1) seq_kernel(
    const float* __restrict__ act,  const float* __restrict__ noise,
    const float* __restrict__ b_p1, const float* __restrict__ b_hh,
    const float* __restrict__ b_p2, const float* __restrict__ b_q2,
    const float* __restrict__ b_ih, float* __restrict__ out)
{
    extern __shared__ u64 smu[];
    u64* h2   = smu;             // [2048] dup h
    u64* G1p  = smu + 2048;      // [2048] dup elu(prior hidden)
    u64* G1q  = smu + 4096;      // [2048] dup elu(post hidden)
    u64* x2   = smu + 6144;      // [320]  dup [z|a]
    u64* part = smu + 6464;      // [5120] S1 cross-half partials / S2 partials
    float* Gh = (float*)(smu + 11584);  // [6144]
    float* gi = Gh + 6144;              // [6144]
    float* pq = gi + 6144;              // [1024] pm|ps|qm|qs
    float* qb = pq + 1024;              // [2][2048] q1emb double buffer
    float* hF = (float*)h2;             // h value = hF[2*i]

    int p  = threadIdx.x;
    int b0 = blockIdx.x * 8;

    // S1 thread mapping
    int ph   = (p >= 320);          // k-half
    int q    = p - (ph ? 320 : 0);  // col quad 0..319
    int s1n0 = 4 * q;               // first col
    int r0e  = 4 * ph;              // epilogue rows r0e..r0e+3

    for (int i = p; i < 2048; i += SQ_T) h2[i] = 0ull;
    // initial q1emb buffer (t=0) into qb[0]
    if (p < 512) {
        int r = p >> 6, c4 = (p & 63) * 4;
        *(float4*)&qb[r * 256 + c4] =
            __ldcs((const float4*)&g_q1emb[(long)(b0 + r) * Tn * 256 + c4]);
    }

    // hoisted per-thread constants
    float4 bias1 = make_float4(0.f, 0.f, 0.f, 0.f);
    if (s1n0 < 256)       bias1 = *(const float4*)&b_p1[s1n0];
    else if (s1n0 >= 512) bias1 = *(const float4*)&b_hh[s1n0 - 512];
    float2 bih = make_float2(0.f, 0.f);
    if (p < 384) bih = *(const float2*)&b_ih[2 * p];

    int s2_u = p & 63, s2_kb = p >> 6;          // valid for p<512
    int s2_c = s2_u & 31;
    float2 s2_b = make_float2(0.f, 0.f);
    if (p < 512) s2_b = (s2_u < 32) ? *(const float2*)&b_p2[2 * s2_c]
                                    : *(const float2*)&b_q2[2 * s2_c];
    __syncthreads();

    const ulonglong2* WPQ = (const ulonglong2*)g_Wpq2;    // [kp][64]
    const ulonglong2* WI  = (const ulonglong2*)g_Wih2;    // [kp][384]
    const ulonglong2* H2v = (const ulonglong2*)h2;        // [r][128]
    const ulonglong2* X2v = (const ulonglong2*)x2;        // [r][20]
    // weight base for this thread's k-half + col quad
    const ulonglong2* WQ  = (const ulonglong2*)g_Wbig4 + ph * 64 * 640 + q * 2;
    const ulonglong2* Hb  = H2v + ph * 64;   // k-offset; + r*128 per row

    for (int tt = 0; tt < Tn; tt++) {
        const float* qcur = qb + (tt & 1) * 2048;
        float*       qnxt = qb + ((tt + 1) & 1) * 2048;

        // --- prefetch (consumed in S2.5, latency hidden under S1) ---
        float ep = 0.f, av = 0.f;
        if (p < 256) {
            int r = p >> 5, s = p & 31;
            ep = __ldcs(&noise[(long)tt * 32768 + (b0 + r) * 32 + s]);
        } else if (p < 320) {
            int qq = p - 256, r = qq >> 3, j = qq & 7;
            av = __ldcs(&act[(long)(b0 + r) * 1024 + tt * 8 + j]);
        }

        // ===== S1 mainloop: acc[8][2] over this thread's k-half =====
        u64 acc[8][2];
        #pragma unroll
        for (int r = 0; r < 8; r++) { acc[r][0] = 0ull; acc[r][1] = 0ull; }
        {
            ulonglong2 a0 = WQ[0], a1 = WQ[1], c0 = WQ[640], c1 = WQ[641];
            for (int it = 0; it < 32; it++) {
                const ulonglong2* Wn = WQ + (it + 1) * 1280;
                ulonglong2 na0 = Wn[0], na1 = Wn[1], nc0 = Wn[640], nc1 = Wn[641];
                int kof = 2 * it;
                #pragma unroll
                for (int r = 0; r < 8; r++) {
                    ulonglong2 h01 = Hb[r * 128 + kof];
                    ulonglong2 h23 = Hb[r * 128 + kof + 1];
                    fma2(acc[r][0], h01.x, a0.x); fma2(acc[r][1], h01.x, a0.y);
                    fma2(acc[r][0], h01.y, a1.x); fma2(acc[r][1], h01.y, a1.y);
                    fma2(acc[r][0], h23.x, c0.x); fma2(acc[r][1], h23.x, c0.y);
                    fma2(acc[r][0], h23.y, c1.x); fma2(acc[r][1], h23.y, c1.y);
                }
                a0 = na0; a1 = na1; c0 = nc0; c1 = nc1;
            }
        }
        // store partials of the OTHER half's epilogue rows
        {
            int orow = 4 * (1 - ph);
            #pragma unroll
            for (int rr = 0; rr < 4; rr++) {
                *(ulonglong2*)&part[((ph * 4 + rr) * 320 + q) * 2] =
                    make_ulonglong2(acc[orow + rr][0], acc[orow + rr][1]);
            }
        }
        __syncthreads();

        // ===== S1 reduce + epilogue (rows r0e..r0e+3) =====
        {
            u64 fin[4][2];
            #pragma unroll
            for (int rr = 0; rr < 4; rr++) {
                ulonglong2 pv = *(const ulonglong2*)
                    &part[(((1 - ph) * 4 + rr) * 320 + q) * 2];
                fin[rr][0] = add2(acc[r0e + rr][0], pv.x);
                fin[rr][1] = add2(acc[r0e + rr][1], pv.y);
            }
            if (s1n0 < 256) {
                #pragma unroll
                for (int rr = 0; rr < 4; rr++) {
                    float2 a0 = upk(fin[rr][0]), a1 = upk(fin[rr][1]);
                    ulonglong2* E = (ulonglong2*)(G1p + (r0e + rr) * 256 + s1n0);
                    E[0] = make_ulonglong2(pk2(eluf(a0.x + bias1.x)), pk2(eluf(a0.y + bias1.y)));
                    E[1] = make_ulonglong2(pk2(eluf(a1.x + bias1.z)), pk2(eluf(a1.y + bias1.w)));
                }
            } else if (s1n0 < 512) {
                #pragma unroll
                for (int rr = 0; rr < 4; rr++) {
                    float4 qv = *(const float4*)&qcur[(r0e + rr) * 256 + (s1n0 - 256)];
                    float2 a0 = upk(fin[rr][0]), a1 = upk(fin[rr][1]);
                    ulonglong2* E = (ulonglong2*)(G1q + (r0e + rr) * 256 + (s1n0 - 256));
                    E[0] = make_ulonglong2(pk2(eluf(a0.x + qv.x)), pk2(eluf(a0.y + qv.y)));
                    E[1] = make_ulonglong2(pk2(eluf(a1.x + qv.z)), pk2(eluf(a1.y + qv.w)));
                }
            } else {
                #pragma unroll
                for (int rr = 0; rr < 4; rr++) {
                    float2 a0 = upk(fin[rr][0]), a1 = upk(fin[rr][1]);
                    *(float4*)&Gh[(r0e + rr) * 768 + (s1n0 - 512)] =
                        make_float4(a0.x + bias1.x, a0.y + bias1.y,
                                    a1.x + bias1.z, a1.y + bias1.w);
                }
            }
        }
        __syncthreads();

        // ==== S2 partials (p<512); p>=512: h-out + next-q1emb prefetch ====
        if (p < 512) {
            const ulonglong2* INv = (const ulonglong2*)((s2_u < 32) ? G1p : G1q);
            u64 a8[8];
            #pragma unroll
            for (int r = 0; r < 8; r++) a8[r] = 0ull;
            int kbase = s2_kb * 16;
            #pragma unroll 4
            for (int qq = 0; qq < 16; qq++) {
                int kpg = kbase + qq;
                ulonglong2 w = WPQ[kpg * 64 + s2_u];
                #pragma unroll
                for (int r = 0; r < 8; r++) {
                    ulonglong2 iv = INv[r * 128 + kpg];
                    fma2(a8[r], iv.x, w.x);
                    fma2(a8[r], iv.y, w.y);
                }
            }
            #pragma unroll
            for (int r = 0; r < 8; r++)
                part[(s2_kb * 8 + r) * 64 + s2_u] = a8[r];
        } else {
            int idx = p - 512;   // 0..127
            #pragma unroll
            for (int j = 0; j < 16; j++) {
                int i = idx + j * 128, r = i >> 8, d = i & 255;
                __stcs(&out[(long)(b0 + r) * 53248 + tt * 416 + d], hF[2 * i]);
            }
            if (tt + 1 < Tn) {   // prefetch next step's q1emb into other buffer
                #pragma unroll
                for (int j = 0; j < 4; j++) {
                    int i = idx + j * 128;          // 0..511 float4 chunks
                    int r = i >> 6, c4 = (i & 63) * 4;
                    *(float4*)&qnxt[r * 256 + c4] =
                        __ldcs((const float4*)&g_q1emb[((long)(b0 + r) * Tn + tt + 1) * 256 + c4]);
                }
            }
        }
        __syncthreads();

        // ================= S2 reduce -> pq =================
        if (p < 512) {
            int r = p >> 6;
            u64 s = part[r * 64 + s2_u];
            #pragma unroll
            for (int kb = 1; kb < 8; kb++)
                s = add2(s, part[(kb * 8 + r) * 64 + s2_u]);
            float2 v = upk(s);
            v.x += s2_b.x; v.y += s2_b.y;
            if (s2_c >= 16) { v.x = __expf(clipf(v.x)); v.y = __expf(clipf(v.y)); }
            *(float2*)&pq[r * 128 + (s2_u < 32 ? 0 : 64) + 2 * s2_c] = v;
        }
        __syncthreads();

        // ========== S2.5: z + act staging; pq out on idle threads ==========
        if (p < 256) {
            int r = p >> 5, s = p & 31;
            float qm = pq[r * 128 + 64 + s], qs = pq[r * 128 + 96 + s];
            float z  = fmaf(qs, ep, qm);
            x2[r * 40 + s] = pk2(z);
            __stcs(&out[(long)(b0 + r) * 53248 + tt * 416 + 256 + s], z);
        } else if (p < 320) {
            int qq = p - 256, r = qq >> 3, j = qq & 7;
            x2[r * 40 + 32 + j] = pk2(av);
        } else if (p < 576) {
            int i = p - 320;         // 0..255 float4 chunks of pq
            int r = i >> 5, cc = 4 * (i & 31);
            __stcs((float4*)&out[(long)(b0 + r) * 53248 + tt * 416 + 288 + cc],
                   *(const float4*)&pq[r * 128 + cc]);
        }
        __syncthreads();

        // ================= S3: gi = x @ W_ih (p<384) =================
        if (p < 384) {
            u64 a3[8];
            #pragma unroll
            for (int r = 0; r < 8; r++) a3[r] = 0ull;
            #pragma unroll 4
            for (int kp = 0; kp < 20; kp++) {
                ulonglong2 w = WI[kp * 384 + p];
                #pragma unroll
                for (int r = 0; r < 8; r++) {
                    ulonglong2 iv = X2v[r * 20 + kp];
                    fma2(a3[r], iv.x, w.x);
                    fma2(a3[r], iv.y, w.y);
                }
            }
            #pragma unroll
            for (int r = 0; r < 8; r++) {
                float2 a0 = upk(a3[r]);
                *(float2*)&gi[r * 768 + 2 * p] = make_float2(a0.x + bih.x, a0.y + bih.y);
            }
        }
        __syncthreads();

        // ================= S4: GRU gates -> new h =================
        for (int i = p; i < 2048; i += SQ_T) {
            int r = i >> 8, d = i & 255;
            float gir = gi[r * 768 + d];
            float giz = gi[r * 768 + 256 + d];
            float gin = gi[r * 768 + 512 + d];
            float ghr = Gh[r * 768 + d];
            float ghz = Gh[r * 768 + 256 + d];
            float ghn = Gh[r * 768 + 512 + d];
            float rg = sigf(gir + ghr);
            float ug = sigf(giz + ghz);
            float ng = tanf_(gin + rg * ghn);
            float ho = hF[2 * i];
            h2[i] = pk2((1.f - ug) * ng + ug * ho);
        }
        __syncthreads();
    }
}

// ---------------------------------------------------------------------------
extern "C" void kernel_launch(void* const* d_in, const int* in_sizes, int n_in,
                              void* d_out, int out_size)
{
    const float* obs = (const float*)d_in[0];
    const float* act = (const float*)d_in[1];
    const float* noi = (const float*)d_in[2];
    const float* We1 = (const float*)d_in[3];
    const float* be1 = (const float*)d_in[4];
    const float* We2 = (const float*)d_in[5];
    const float* be2 = (const float*)d_in[6];
    const float* Wih = (const float*)d_in[7];
    const float* Whh = (const float*)d_in[8];
    const float* bih = (const float*)d_in[9];
    const float* bhh = (const float*)d_in[10];
    const float* Wp1 = (const float*)d_in[11];
    const float* bp1 = (const float*)d_in[12];
    const float* Wp2 = (const float*)d_in[13];
    const float* bp2 = (const float*)d_in[14];
    const float* Wq1 = (const float*)d_in[15];
    const float* bq1 = (const float*)d_in[16];
    const float* Wq2 = (const float*)d_in[17];
    const float* bq2 = (const float*)d_in[18];
    float* out = (float*)d_out;

    cudaFuncSetAttribute(emb_kernel, cudaFuncAttributeMaxDynamicSharedMemorySize, EMB_SMEM);
    cudaFuncSetAttribute(seq_kernel, cudaFuncAttributeMaxDynamicSharedMemorySize, SEQ_SMEM);

    prep_kernel<<<64, 256>>>(Wp1, Wq1, Whh, Wih, Wp2, Wq2, We1, We2);
    emb_kernel<<<(Bsz * Tn) / 32, EMB_T, EMB_SMEM>>>(obs, be1, be2, bq1);
    seq_kernel<<<Bsz / 8, SQ_T, SEQ_SMEM>>>(act, noi, bp1, bhh, bp2, bq2, bih, out);
}